// round 1
// baseline (speedup 1.0000x reference)
#include <cuda_runtime.h>
#include <cfloat>
#include <climits>

// Problem shape (fixed by setup_inputs)
#define NCOLS 1000
#define NVEC  250          // NCOLS / 4, exact
#define TPB   256          // threads per row-CTA (8 warps)

struct Top2 {
    float t1;  // max
    float t2;  // second max
    int   i1;  // argmax (first occurrence / smallest index on ties)
};

// Merge candidate (o1 with index oi, plus its own second o2) into accumulator a.
// Result = top-2 of the union. Valid because o2 <= o1 always.
__device__ __forceinline__ void top2_merge(Top2& a, float o1, float o2, int oi) {
    if (o1 > a.t1 || (o1 == a.t1 && oi < a.i1)) {
        a.t2 = fmaxf(a.t1, o2);
        a.t1 = o1;
        a.i1 = oi;
    } else {
        a.t2 = fmaxf(a.t2, o1);
    }
}

__device__ __forceinline__ void top2_warp_reduce(Top2& a) {
    #pragma unroll
    for (int off = 16; off > 0; off >>= 1) {
        float o1 = __shfl_xor_sync(0xFFFFFFFFu, a.t1, off);
        float o2 = __shfl_xor_sync(0xFFFFFFFFu, a.t2, off);
        int   oi = __shfl_xor_sync(0xFFFFFFFFu, a.i1, off);
        top2_merge(a, o1, o2, oi);
    }
}

__global__ __launch_bounds__(TPB, 8)
void netsat1_kernel(const float* __restrict__ y1,
                    const float* __restrict__ y2,
                    float* __restrict__ out)
{
    const int row = blockIdx.x;
    const int t   = threadIdx.x;
    const int wid = t >> 5;
    const int lid = t & 31;

    const float4* r1 = reinterpret_cast<const float4*>(y1 + (size_t)row * NCOLS);
    const float4* r2 = reinterpret_cast<const float4*>(y2 + (size_t)row * NCOLS);

    const bool active = (t < NVEC);

    float a[4], b[4];
    if (active) {
        float4 va = __ldg(&r1[t]);
        float4 vb = __ldg(&r2[t]);
        a[0] = va.x; a[1] = va.y; a[2] = va.z; a[3] = va.w;
        b[0] = vb.x; b[1] = vb.y; b[2] = vb.z; b[3] = vb.w;
    } else {
        #pragma unroll
        for (int k = 0; k < 4; ++k) { a[k] = -FLT_MAX; b[k] = -FLT_MAX; }
    }

    const int base = t * 4;

    // Per-thread top-2 of the 4 cached elements (inactive threads hold -FLT_MAX)
    Top2 t2a = { a[0], -FLT_MAX, active ? base : INT_MAX };
    Top2 t2b = { b[0], -FLT_MAX, active ? base : INT_MAX };
    #pragma unroll
    for (int k = 1; k < 4; ++k) {
        top2_merge(t2a, a[k], -FLT_MAX, active ? base + k : INT_MAX);
        top2_merge(t2b, b[k], -FLT_MAX, active ? base + k : INT_MAX);
    }

    // Warp-level butterfly reduce
    top2_warp_reduce(t2a);
    top2_warp_reduce(t2b);

    __shared__ Top2 s1[TPB / 32];
    __shared__ Top2 s2[TPB / 32];
    __shared__ Top2 fin1, fin2;
    __shared__ float smax[TPB / 32];

    if (lid == 0) { s1[wid] = t2a; s2[wid] = t2b; }
    __syncthreads();

    if (wid == 0) {
        Top2 ra, rb;
        if (lid < TPB / 32) { ra = s1[lid]; rb = s2[lid]; }
        else {
            ra.t1 = ra.t2 = -FLT_MAX; ra.i1 = INT_MAX;
            rb.t1 = rb.t2 = -FLT_MAX; rb.i1 = INT_MAX;
        }
        top2_warp_reduce(ra);
        top2_warp_reduce(rb);
        if (lid == 0) { fin1 = ra; fin2 = rb; }
    }
    __syncthreads();

    const float t1_1 = fin1.t1, t2_1 = fin1.t2; const int i1_1 = fin1.i1;
    const float t1_2 = fin2.t1, t2_2 = fin2.t2; const int i1_2 = fin2.i1;

    // Second phase from registers: m = max_j min(y1[j]-loo1[j], y2[j]-loo2[j])
    float m = -FLT_MAX;
    if (active) {
        #pragma unroll
        for (int k = 0; k < 4; ++k) {
            const int col = base + k;
            const float loo1 = (col == i1_1) ? t2_1 : t1_1;
            const float loo2 = (col == i1_2) ? t2_2 : t1_2;
            m = fmaxf(m, fminf(a[k] - loo1, b[k] - loo2));
        }
    }

    // Block max reduce
    #pragma unroll
    for (int off = 16; off > 0; off >>= 1)
        m = fmaxf(m, __shfl_xor_sync(0xFFFFFFFFu, m, off));
    if (lid == 0) smax[wid] = m;
    __syncthreads();
    if (t == 0) {
        float r = smax[0];
        #pragma unroll
        for (int w = 1; w < TPB / 32; ++w) r = fmaxf(r, smax[w]);
        out[row] = r;
    }
}

extern "C" void kernel_launch(void* const* d_in, const int* in_sizes, int n_in,
                              void* d_out, int out_size)
{
    const float* y1 = (const float*)d_in[0];
    const float* y2 = (const float*)d_in[1];
    float* out = (float*)d_out;

    const int B = in_sizes[0] / NCOLS;   // 16384
    netsat1_kernel<<<B, TPB>>>(y1, y2, out);
}

// round 2
// speedup vs baseline: 1.5005x; 1.5005x over previous
#include <cuda_runtime.h>
#include <cfloat>

#define NCOLS 1000
#define NVEC  250          // float4s per row per array
#define TPB   128
#define NWARP (TPB / 32)

// Order-preserving float<->uint mapping (total order, works for all finite values)
__device__ __forceinline__ unsigned ford(float f) {
    unsigned u = __float_as_uint(f);
    return (u & 0x80000000u) ? ~u : (u | 0x80000000u);
}
__device__ __forceinline__ float funord(unsigned u) {
    return __uint_as_float((u & 0x80000000u) ? (u ^ 0x80000000u) : ~u);
}

// Exact warp top-2 in ordered-uint domain. In: per-lane (o1 >= o2).
// Out: every lane holds the warp-wide (r1, r2).
__device__ __forceinline__ void warp_top2(unsigned& o1, unsigned& o2) {
    unsigned r1  = __reduce_max_sync(0xFFFFFFFFu, o1);
    unsigned bal = __ballot_sync(0xFFFFFFFFu, o1 == r1);
    unsigned u   = (o1 == r1) ? o2 : o1;
    unsigned r2  = __reduce_max_sync(0xFFFFFFFFu, u);
    if (__popc(bal) > 1) r2 = r1;   // max duplicated across lanes -> t2 == t1 (exact)
    o1 = r1; o2 = r2;
}

// Branchless exact top-2 of 8 values (tournament, all FMNMX)
__device__ __forceinline__ void thread_top2_8(const float v[8], float& t1, float& t2) {
    float m0 = fmaxf(v[0], v[1]), n0 = fminf(v[0], v[1]);
    float m1 = fmaxf(v[2], v[3]), n1 = fminf(v[2], v[3]);
    float m2 = fmaxf(v[4], v[5]), n2 = fminf(v[4], v[5]);
    float m3 = fmaxf(v[6], v[7]), n3 = fminf(v[6], v[7]);
    float a1 = fmaxf(m0, m1), a2 = fmaxf(fminf(m0, m1), fmaxf(n0, n1));
    float b1 = fmaxf(m2, m3), b2 = fmaxf(fminf(m2, m3), fmaxf(n2, n3));
    t1 = fmaxf(a1, b1);
    t2 = fmaxf(fminf(a1, b1), fmaxf(a2, b2));
}

__global__ __launch_bounds__(TPB)
void netsat1_kernel(const float* __restrict__ y1,
                    const float* __restrict__ y2,
                    float* __restrict__ out)
{
    const int row = blockIdx.x;
    const int t   = threadIdx.x;
    const int wid = t >> 5;
    const int lid = t & 31;

    const float4* r1 = reinterpret_cast<const float4*>(y1 + (size_t)row * NCOLS);
    const float4* r2 = reinterpret_cast<const float4*>(y2 + (size_t)row * NCOLS);

    // Each thread: float4 at t (always valid, t<128<250) and at t+128 (valid t<122)
    float a[8], b[8];
    {
        float4 va = __ldg(&r1[t]);
        float4 vb = __ldg(&r2[t]);
        a[0]=va.x; a[1]=va.y; a[2]=va.z; a[3]=va.w;
        b[0]=vb.x; b[1]=vb.y; b[2]=vb.z; b[3]=vb.w;
    }
    if (t < NVEC - TPB) {
        float4 va = __ldg(&r1[t + TPB]);
        float4 vb = __ldg(&r2[t + TPB]);
        a[4]=va.x; a[5]=va.y; a[6]=va.z; a[7]=va.w;
        b[4]=vb.x; b[5]=vb.y; b[6]=vb.z; b[7]=vb.w;
    } else {
        #pragma unroll
        for (int k = 4; k < 8; ++k) { a[k] = -FLT_MAX; b[k] = -FLT_MAX; }
    }

    // --- Pass 1: block top-2 (values only) for each array ---
    float ta1, ta2, tb1, tb2;
    thread_top2_8(a, ta1, ta2);
    thread_top2_8(b, tb1, tb2);

    unsigned oa1 = ford(ta1), oa2 = ford(ta2);
    unsigned ob1 = ford(tb1), ob2 = ford(tb2);
    warp_top2(oa1, oa2);
    warp_top2(ob1, ob2);

    __shared__ uint2 sw1[NWARP], sw2[NWARP];
    __shared__ unsigned fin[4];
    __shared__ unsigned smax[NWARP];

    if (lid == 0) { sw1[wid] = make_uint2(oa1, oa2); sw2[wid] = make_uint2(ob1, ob2); }
    __syncthreads();

    if (wid == 0) {
        uint2 pa = (lid < NWARP) ? sw1[lid] : make_uint2(0u, 0u);
        uint2 pb = (lid < NWARP) ? sw2[lid] : make_uint2(0u, 0u);
        unsigned x1 = pa.x, x2 = pa.y, z1 = pb.x, z2 = pb.y;
        warp_top2(x1, x2);
        warp_top2(z1, z2);
        if (lid == 0) { fin[0] = x1; fin[1] = x2; fin[2] = z1; fin[3] = z2; }
    }
    __syncthreads();

    const float t1_1 = funord(fin[0]);
    const float t2_1 = funord(fin[1]);
    const float t1_2 = funord(fin[2]);
    const float t2_2 = funord(fin[3]);

    // --- Pass 2 (from registers), shifted domain:
    // min(y1-t1_1, y2-t1_2) = min(y1, y2 + d) - t1_1,  d = t1_1 - t1_2
    const float d = t1_1 - t1_2;
    float m = -FLT_MAX;
    bool anyeq = false;
    #pragma unroll
    for (int k = 0; k < 8; ++k) {
        m = fmaxf(m, fminf(a[k], b[k] + d));
        anyeq |= (a[k] == t1_1) || (b[k] == t1_2);
    }
    // Cold fixup for the (at most 2) argmax columns; base cand <= corrected cand,
    // so max(base, corrected) is exact.
    if (anyeq) {
        #pragma unroll
        for (int k = 0; k < 8; ++k) {
            if (a[k] == t1_1 || b[k] == t1_2) {
                float loo1 = (a[k] == t1_1) ? t2_1 : t1_1;
                float loo2 = (b[k] == t1_2) ? t2_2 : t1_2;
                float c = fminf(a[k] - loo1, b[k] - loo2) + t1_1;  // shifted
                m = fmaxf(m, c);
            }
        }
    }

    // --- Block max reduce of m ---
    unsigned om = __reduce_max_sync(0xFFFFFFFFu, ford(m));
    if (lid == 0) smax[wid] = om;
    __syncthreads();
    if (t == 0) {
        unsigned r = smax[0];
        #pragma unroll
        for (int w = 1; w < NWARP; ++w) r = max(r, smax[w]);
        out[row] = funord(r) - t1_1;   // un-shift
    }
}

extern "C" void kernel_launch(void* const* d_in, const int* in_sizes, int n_in,
                              void* d_out, int out_size)
{
    const float* y1 = (const float*)d_in[0];
    const float* y2 = (const float*)d_in[1];
    float* out = (float*)d_out;

    const int B = in_sizes[0] / NCOLS;   // 16384
    netsat1_kernel<<<B, TPB>>>(y1, y2, out);
}

// round 3
// speedup vs baseline: 1.6007x; 1.0667x over previous
#include <cuda_runtime.h>
#include <cfloat>

#define NCOLS 1000
#define NVEC  250          // float4s per row per array
#define TPB   128
#define NWARP (TPB / 32)

// Order-preserving float<->uint mapping
__device__ __forceinline__ unsigned ford(float f) {
    unsigned u = __float_as_uint(f);
    return ((int)u < 0) ? ~u : (u | 0x80000000u);
}
__device__ __forceinline__ float funord(unsigned u) {
    return __uint_as_float(((int)u < 0) ? (u ^ 0x80000000u) : ~u);
}

// Exact warp top-2 in ordered-uint domain (per-lane o1 >= o2 on entry).
__device__ __forceinline__ void warp_top2(unsigned& o1, unsigned& o2) {
    unsigned r1  = __reduce_max_sync(0xFFFFFFFFu, o1);
    unsigned bal = __ballot_sync(0xFFFFFFFFu, o1 == r1);
    unsigned u   = (o1 == r1) ? o2 : o1;
    unsigned r2  = __reduce_max_sync(0xFFFFFFFFu, u);
    if (__popc(bal) > 1) r2 = r1;   // duplicated max across lanes -> t2 == t1
    o1 = r1; o2 = r2;
}

// Branchless exact top-2 of 8 values (tournament, FMNMX only)
__device__ __forceinline__ void thread_top2_8(const float v[8], float& t1, float& t2) {
    float m0 = fmaxf(v[0], v[1]), n0 = fminf(v[0], v[1]);
    float m1 = fmaxf(v[2], v[3]), n1 = fminf(v[2], v[3]);
    float m2 = fmaxf(v[4], v[5]), n2 = fminf(v[4], v[5]);
    float m3 = fmaxf(v[6], v[7]), n3 = fminf(v[6], v[7]);
    float a1 = fmaxf(m0, m1), a2 = fmaxf(fminf(m0, m1), fmaxf(n0, n1));
    float b1 = fmaxf(m2, m3), b2 = fmaxf(fminf(m2, m3), fmaxf(n2, n3));
    t1 = fmaxf(a1, b1);
    t2 = fmaxf(fminf(a1, b1), fmaxf(a2, b2));
}

// Merge (t1,t2) pair q into accumulator (t1,t2)
__device__ __forceinline__ void pair_merge(float& t1, float& t2, float q1, float q2) {
    float mn = fminf(t1, q1);
    t1 = fmaxf(t1, q1);
    t2 = fmaxf(mn, fmaxf(t2, q2));
}

__global__ __launch_bounds__(TPB, 16)
void netsat1_kernel(const float* __restrict__ y1,
                    const float* __restrict__ y2,
                    float* __restrict__ out)
{
    const int row = blockIdx.x;
    const int t   = threadIdx.x;
    const int wid = t >> 5;
    const int lid = t & 31;

    const float4* r1 = reinterpret_cast<const float4*>(y1 + (size_t)row * NCOLS);
    const float4* r2 = reinterpret_cast<const float4*>(y2 + (size_t)row * NCOLS);

    float a[8], b[8];
    {
        float4 va = __ldg(&r1[t]);
        float4 vb = __ldg(&r2[t]);
        a[0]=va.x; a[1]=va.y; a[2]=va.z; a[3]=va.w;
        b[0]=vb.x; b[1]=vb.y; b[2]=vb.z; b[3]=vb.w;
    }
    if (t < NVEC - TPB) {
        float4 va = __ldg(&r1[t + TPB]);
        float4 vb = __ldg(&r2[t + TPB]);
        a[4]=va.x; a[5]=va.y; a[6]=va.z; a[7]=va.w;
        b[4]=vb.x; b[5]=vb.y; b[6]=vb.z; b[7]=vb.w;
    } else {
        #pragma unroll
        for (int k = 4; k < 8; ++k) { a[k] = -FLT_MAX; b[k] = -FLT_MAX; }
    }

    // --- Pass 1: per-thread exact top-2, then warp top-2 ---
    float ta1, ta2, tb1, tb2;
    thread_top2_8(a, ta1, ta2);
    thread_top2_8(b, tb1, tb2);

    unsigned oa1 = ford(ta1), oa2 = ford(ta2);
    unsigned ob1 = ford(tb1), ob2 = ford(tb2);
    warp_top2(oa1, oa2);
    warp_top2(ob1, ob2);

    __shared__ float4 sw[NWARP];
    __shared__ unsigned smax[NWARP];

    if (lid == 0)
        sw[wid] = make_float4(funord(oa1), funord(oa2), funord(ob1), funord(ob2));
    __syncthreads();

    // All threads redundantly merge the 4 warp pairs (no second sync round)
    float4 s0 = sw[0];
    float t1_1 = s0.x, t2_1 = s0.y, t1_2 = s0.z, t2_2 = s0.w;
    #pragma unroll
    for (int w = 1; w < NWARP; ++w) {
        float4 s = sw[w];
        pair_merge(t1_1, t2_1, s.x, s.y);
        pair_merge(t1_2, t2_2, s.z, s.w);
    }

    // --- Pass 2 (registers), shifted domain:
    // min(y1-t1_1, y2-t1_2) = min(y1, y2 + d) - t1_1,  d = t1_1 - t1_2
    const float d = t1_1 - t1_2;
    float m = -FLT_MAX;
    #pragma unroll
    for (int k = 0; k < 8; ++k)
        m = fmaxf(m, fminf(a[k], b[k] + d));

    // Fixup needed iff this thread holds a row-argmax element of either array.
    if ((ta1 == t1_1) || (tb1 == t1_2)) {
        #pragma unroll
        for (int k = 0; k < 8; ++k) {
            if (a[k] == t1_1 || b[k] == t1_2) {
                float loo1 = (a[k] == t1_1) ? t2_1 : t1_1;
                float loo2 = (b[k] == t1_2) ? t2_2 : t1_2;
                m = fmaxf(m, fminf(a[k] - loo1, b[k] - loo2) + t1_1);  // shifted
            }
        }
    }

    // --- Block max reduce of m ---
    unsigned om = __reduce_max_sync(0xFFFFFFFFu, ford(m));
    if (lid == 0) smax[wid] = om;
    __syncthreads();
    if (t == 0) {
        unsigned r = smax[0];
        #pragma unroll
        for (int w = 1; w < NWARP; ++w) r = max(r, smax[w]);
        out[row] = funord(r) - t1_1;   // un-shift
    }
}

extern "C" void kernel_launch(void* const* d_in, const int* in_sizes, int n_in,
                              void* d_out, int out_size)
{
    const float* y1 = (const float*)d_in[0];
    const float* y2 = (const float*)d_in[1];
    float* out = (float*)d_out;

    const int B = in_sizes[0] / NCOLS;   // 16384
    netsat1_kernel<<<B, TPB>>>(y1, y2, out);
}

// round 4
// speedup vs baseline: 1.7548x; 1.0963x over previous
#include <cuda_runtime.h>
#include <cfloat>

#define NCOLS 1000
#define NVEC  250          // float4s per row per array
#define TPB   64
#define NWARP (TPB / 32)   // 2

// Order-preserving float<->uint mapping
__device__ __forceinline__ unsigned ford(float f) {
    unsigned u = __float_as_uint(f);
    return ((int)u < 0) ? ~u : (u | 0x80000000u);
}
__device__ __forceinline__ float funord(unsigned u) {
    return __uint_as_float(((int)u < 0) ? (u ^ 0x80000000u) : ~u);
}

// Exact warp top-2 in ordered-uint domain (per-lane o1 >= o2 on entry).
__device__ __forceinline__ void warp_top2(unsigned& o1, unsigned& o2) {
    unsigned r1  = __reduce_max_sync(0xFFFFFFFFu, o1);
    unsigned bal = __ballot_sync(0xFFFFFFFFu, o1 == r1);
    unsigned u   = (o1 == r1) ? o2 : o1;
    unsigned r2  = __reduce_max_sync(0xFFFFFFFFu, u);
    if (__popc(bal) > 1) r2 = r1;   // duplicated max across lanes -> t2 == t1
    o1 = r1; o2 = r2;
}

// Branchless exact top-2 of 8 (FMNMX tournament)
__device__ __forceinline__ void top2_8(const float* v, float& t1, float& t2) {
    float m0 = fmaxf(v[0], v[1]), n0 = fminf(v[0], v[1]);
    float m1 = fmaxf(v[2], v[3]), n1 = fminf(v[2], v[3]);
    float m2 = fmaxf(v[4], v[5]), n2 = fminf(v[4], v[5]);
    float m3 = fmaxf(v[6], v[7]), n3 = fminf(v[6], v[7]);
    float a1 = fmaxf(m0, m1), a2 = fmaxf(fminf(m0, m1), fmaxf(n0, n1));
    float b1 = fmaxf(m2, m3), b2 = fmaxf(fminf(m2, m3), fmaxf(n2, n3));
    t1 = fmaxf(a1, b1);
    t2 = fmaxf(fminf(a1, b1), fmaxf(a2, b2));
}

// Exact top-2 of 16 = merge of two top2_8
__device__ __forceinline__ void top2_16(const float* v, float& t1, float& t2) {
    float p1, p2, q1, q2;
    top2_8(v, p1, p2);
    top2_8(v + 8, q1, q2);
    t1 = fmaxf(p1, q1);
    t2 = fmaxf(fminf(p1, q1), fmaxf(p2, q2));
}

// Merge (t1,t2) pair q into accumulator
__device__ __forceinline__ void pair_merge(float& t1, float& t2, float q1, float q2) {
    float mn = fminf(t1, q1);
    t1 = fmaxf(t1, q1);
    t2 = fmaxf(mn, fmaxf(t2, q2));
}

__global__ __launch_bounds__(TPB, 12)
void netsat1_kernel(const float* __restrict__ y1,
                    const float* __restrict__ y2,
                    float* __restrict__ out)
{
    const int row = blockIdx.x;
    const int t   = threadIdx.x;
    const int wid = t >> 5;
    const int lid = t & 31;

    const float4* r1 = reinterpret_cast<const float4*>(y1 + (size_t)row * NCOLS);
    const float4* r2 = reinterpret_cast<const float4*>(y2 + (size_t)row * NCOLS);

    // 4 float4 chunks per array: t, t+64, t+128 always valid (<250); t+192 valid for t<58
    float a[16], b[16];
    const bool c3 = (t < NVEC - 3 * TPB);   // t < 58
    {
        float4 v0 = __ldg(&r1[t]);
        float4 v1 = __ldg(&r1[t + TPB]);
        float4 v2 = __ldg(&r1[t + 2 * TPB]);
        float4 w0 = __ldg(&r2[t]);
        float4 w1 = __ldg(&r2[t + TPB]);
        float4 w2 = __ldg(&r2[t + 2 * TPB]);
        float4 v3, w3;
        if (c3) { v3 = __ldg(&r1[t + 3 * TPB]); w3 = __ldg(&r2[t + 3 * TPB]); }
        else    { v3 = make_float4(-FLT_MAX,-FLT_MAX,-FLT_MAX,-FLT_MAX); w3 = v3; }
        a[0]=v0.x; a[1]=v0.y; a[2]=v0.z; a[3]=v0.w;
        a[4]=v1.x; a[5]=v1.y; a[6]=v1.z; a[7]=v1.w;
        a[8]=v2.x; a[9]=v2.y; a[10]=v2.z; a[11]=v2.w;
        a[12]=v3.x; a[13]=v3.y; a[14]=v3.z; a[15]=v3.w;
        b[0]=w0.x; b[1]=w0.y; b[2]=w0.z; b[3]=w0.w;
        b[4]=w1.x; b[5]=w1.y; b[6]=w1.z; b[7]=w1.w;
        b[8]=w2.x; b[9]=w2.y; b[10]=w2.z; b[11]=w2.w;
        b[12]=w3.x; b[13]=w3.y; b[14]=w3.z; b[15]=w3.w;
    }

    // --- Pass 1: per-thread exact top-2 of 16, then warp top-2 ---
    float ta1, ta2, tb1, tb2;
    top2_16(a, ta1, ta2);
    top2_16(b, tb1, tb2);

    unsigned oa1 = ford(ta1), oa2 = ford(ta2);
    unsigned ob1 = ford(tb1), ob2 = ford(tb2);
    warp_top2(oa1, oa2);
    warp_top2(ob1, ob2);

    __shared__ float4 sw[NWARP];
    __shared__ unsigned smax[NWARP];

    if (lid == 0)
        sw[wid] = make_float4(funord(oa1), funord(oa2), funord(ob1), funord(ob2));
    __syncthreads();

    // Merge the 2 warp pairs (redundant in all threads; 8 FMNMX)
    float4 s0 = sw[0], s1 = sw[1];
    float t1_1 = s0.x, t2_1 = s0.y, t1_2 = s0.z, t2_2 = s0.w;
    pair_merge(t1_1, t2_1, s1.x, s1.y);
    pair_merge(t1_2, t2_2, s1.z, s1.w);

    // --- Pass 2 (registers), shifted domain:
    // min(y1-t1_1, y2-t1_2) = min(y1, y2 + d) - t1_1,  d = t1_1 - t1_2
    const float d = t1_1 - t1_2;
    float m = -FLT_MAX;
    #pragma unroll
    for (int k = 0; k < 16; ++k)
        m = fmaxf(m, fminf(a[k], b[k] + d));

    // Fixup iff this thread holds a row-argmax element of either array (cold).
    if ((ta1 == t1_1) || (tb1 == t1_2)) {
        #pragma unroll
        for (int k = 0; k < 16; ++k) {
            if (a[k] == t1_1 || b[k] == t1_2) {
                float loo1 = (a[k] == t1_1) ? t2_1 : t1_1;
                float loo2 = (b[k] == t1_2) ? t2_2 : t1_2;
                m = fmaxf(m, fminf(a[k] - loo1, b[k] - loo2) + t1_1);  // shifted
            }
        }
    }

    // --- Block max reduce of m (2 warps) ---
    unsigned om = __reduce_max_sync(0xFFFFFFFFu, ford(m));
    if (lid == 0) smax[wid] = om;
    __syncthreads();
    if (t == 0)
        out[row] = funord(max(smax[0], smax[1])) - t1_1;   // un-shift
}

extern "C" void kernel_launch(void* const* d_in, const int* in_sizes, int n_in,
                              void* d_out, int out_size)
{
    const float* y1 = (const float*)d_in[0];
    const float* y2 = (const float*)d_in[1];
    float* out = (float*)d_out;

    const int B = in_sizes[0] / NCOLS;   // 16384
    netsat1_kernel<<<B, TPB>>>(y1, y2, out);
}